// round 11
// baseline (speedup 1.0000x reference)
#include <cuda_runtime.h>
#include <cuda_bf16.h>
#include <math.h>
#include <stdint.h>

#define B 256
#define D 128
#define T 512
#define H 256
#define C 10
#define N4 1024

// device scratch (no runtime allocation allowed)
__device__ float g_gates[(size_t)B * T * N4];    // [b][t][4H] fp32, 512 MB
// h double-buffered, bf16 hi/lo, K-INTERLEAVED layout: within each 16-k block,
// element order is pairs (k, k+8): pos(kl) = (kl&1) | (((kl>>1)&3)<<2) | (((kl>>3)&1)<<1)
__device__ unsigned short g_hhi[2][B * H];
__device__ unsigned short g_hlo[2][B * H];
__device__ float g_hfin[B * H];                  // final h fp32 (plain layout)
__device__ unsigned g_bar4[4];                   // per-group step counters

__device__ __forceinline__ float sigf(float x) { return 1.0f / (1.0f + expf(-x)); }

__global__ void reset_kernel() {
    if (threadIdx.x < 4) g_bar4[threadIdx.x] = 0u;
}

__device__ __forceinline__ uint32_t smem_u32(const void* p) {
    uint32_t a;
    asm("{ .reg .u64 t; cvta.to.shared.u64 t, %1; cvt.u32.u64 %0, t; }" : "=r"(a) : "l"(p));
    return a;
}
__device__ __forceinline__ void ldmx4t(uint32_t* r, uint32_t addr) {
    asm volatile("ldmatrix.sync.aligned.m8n8.x4.trans.shared.b16 {%0,%1,%2,%3}, [%4];"
                 : "=r"(r[0]), "=r"(r[1]), "=r"(r[2]), "=r"(r[3]) : "r"(addr));
}
__device__ __forceinline__ void mma16816(float* c,
                                         uint32_t a0, uint32_t a1, uint32_t a2, uint32_t a3,
                                         uint32_t b0, uint32_t b1) {
    asm volatile(
        "mma.sync.aligned.m16n8k16.row.col.f32.bf16.bf16.f32 "
        "{%0,%1,%2,%3}, {%4,%5,%6,%7}, {%8,%9}, {%0,%1,%2,%3};"
        : "+f"(c[0]), "+f"(c[1]), "+f"(c[2]), "+f"(c[3])
        : "r"(a0), "r"(a1), "r"(a2), "r"(a3), "r"(b0), "r"(b1));
}
__device__ __forceinline__ uint32_t pkbf(float x, float y) {
    __nv_bfloat16 a = __float2bfloat16(x), b = __float2bfloat16(y);
    return (uint32_t)reinterpret_cast<unsigned short&>(a) |
           ((uint32_t)reinterpret_cast<unsigned short&>(b) << 16);
}

// ============================== PROJ (mma) ==================================
#define PPITCH 272
#define P_AHI 0
#define P_ALO (128 * PPITCH)
#define P_BHI (2 * 128 * PPITCH)
#define P_BLO (3 * 128 * PPITCH)
#define SMEM_PROJ (4 * 128 * PPITCH)

__global__ __launch_bounds__(256, 1) void projmma_kernel(
    const float* __restrict__ x,
    const float* __restrict__ Wg, const float* __restrict__ Wi,
    const float* __restrict__ Wf, const float* __restrict__ Wo,
    const float* __restrict__ bg, const float* __restrict__ bi,
    const float* __restrict__ bf, const float* __restrict__ bo)
{
    extern __shared__ char psm[];
    const uint32_t sb = smem_u32(psm);

    const int tid = threadIdx.x;
    const int lane = tid & 31;
    const int w = tid >> 5;
    const int wm2 = w & 3;
    const int nq2 = w >> 2;
    const int n0 = blockIdx.x * 128;
    const int m0 = blockIdx.y * 128;
    const int b  = m0 >> 9;
    const int t0 = m0 & 511;
    const int gate = n0 >> 8;
    const int hb = n0 & 255;

    const float* W    = (gate == 0) ? Wg : (gate == 1) ? Wi : (gate == 2) ? Wf : Wo;
    const float* bias = (gate == 0) ? bg : (gate == 1) ? bi : (gate == 2) ? bf : bo;

    #pragma unroll
    for (int i = 0; i < 16; i++) {
        int q = tid + i * 256;
        int k = q >> 5;
        int m4 = q & 31;
        float4 v = __ldcg(reinterpret_cast<const float4*>(
            &x[(size_t)b * (D * T) + k * T + t0 + m4 * 4]));
        float4 wv = __ldg(reinterpret_cast<const float4*>(&W[k * H + hb + m4 * 4]));
        uint32_t hiA0 = pkbf(v.x, v.y), hiA1 = pkbf(v.z, v.w);
        float rx = v.x - __bfloat162float(__float2bfloat16(v.x));
        float ry = v.y - __bfloat162float(__float2bfloat16(v.y));
        float rz = v.z - __bfloat162float(__float2bfloat16(v.z));
        float rw = v.w - __bfloat162float(__float2bfloat16(v.w));
        uint32_t loA0 = pkbf(rx, ry), loA1 = pkbf(rz, rw);
        uint32_t hiB0 = pkbf(wv.x, wv.y), hiB1 = pkbf(wv.z, wv.w);
        float sx = wv.x - __bfloat162float(__float2bfloat16(wv.x));
        float sy = wv.y - __bfloat162float(__float2bfloat16(wv.y));
        float sz = wv.z - __bfloat162float(__float2bfloat16(wv.z));
        float sw = wv.w - __bfloat162float(__float2bfloat16(wv.w));
        uint32_t loB0 = pkbf(sx, sy), loB1 = pkbf(sz, sw);
        uint32_t off = k * PPITCH + m4 * 8;
        *reinterpret_cast<uint2*>(psm + P_AHI + off) = make_uint2(hiA0, hiA1);
        *reinterpret_cast<uint2*>(psm + P_ALO + off) = make_uint2(loA0, loA1);
        *reinterpret_cast<uint2*>(psm + P_BHI + off) = make_uint2(hiB0, hiB1);
        *reinterpret_cast<uint2*>(psm + P_BLO + off) = make_uint2(loB0, loB1);
    }
    __syncthreads();

    const int sel = lane >> 3;
    const int lr  = lane & 7;
    const uint32_t aoff = (uint32_t)(((sel >> 1) * 8 + lr) * PPITCH + (sel & 1) * 16);
    const uint32_t boff = (uint32_t)(((sel & 1) * 8 + lr) * PPITCH + (sel >> 1) * 16);

    float acc[2][8][4] = {};

    #pragma unroll
    for (int kk = 0; kk < 8; kk++) {
        const uint32_t kb = kk * 16 * PPITCH;
        uint32_t ah[2][4], al[2][4], bh[4][4], bl[4][4];
        #pragma unroll
        for (int mf = 0; mf < 2; mf++) {
            uint32_t mcol = (wm2 * 32 + mf * 16) * 2;
            ldmx4t(ah[mf], sb + P_AHI + kb + aoff + mcol);
            ldmx4t(al[mf], sb + P_ALO + kb + aoff + mcol);
        }
        #pragma unroll
        for (int ng = 0; ng < 4; ng++) {
            uint32_t ncol = (nq2 * 64 + ng * 16) * 2;
            ldmx4t(bh[ng], sb + P_BHI + kb + boff + ncol);
            ldmx4t(bl[ng], sb + P_BLO + kb + boff + ncol);
        }
        #pragma unroll
        for (int mf = 0; mf < 2; mf++) {
            #pragma unroll
            for (int ng = 0; ng < 4; ng++) {
                float* c0 = acc[mf][ng * 2];
                float* c1 = acc[mf][ng * 2 + 1];
                mma16816(c0, ah[mf][0], ah[mf][1], ah[mf][2], ah[mf][3], bh[ng][0], bh[ng][1]);
                mma16816(c0, al[mf][0], al[mf][1], al[mf][2], al[mf][3], bh[ng][0], bh[ng][1]);
                mma16816(c0, ah[mf][0], ah[mf][1], ah[mf][2], ah[mf][3], bl[ng][0], bl[ng][1]);
                mma16816(c1, ah[mf][0], ah[mf][1], ah[mf][2], ah[mf][3], bh[ng][2], bh[ng][3]);
                mma16816(c1, al[mf][0], al[mf][1], al[mf][2], al[mf][3], bh[ng][2], bh[ng][3]);
                mma16816(c1, ah[mf][0], ah[mf][1], ah[mf][2], ah[mf][3], bl[ng][2], bl[ng][3]);
            }
        }
    }

    #pragma unroll
    for (int mf = 0; mf < 2; mf++) {
        int m = m0 + wm2 * 32 + mf * 16 + (lane >> 2);
        #pragma unroll
        for (int j = 0; j < 8; j++) {
            int hcol = hb + nq2 * 64 + j * 8 + (lane & 3) * 2;
            float2 bv = *reinterpret_cast<const float2*>(&bias[hcol]);
            int ncol = gate * 256 + hcol;
            *reinterpret_cast<float2*>(&g_gates[(size_t)m * N4 + ncol]) =
                make_float2(acc[mf][j][0] + bv.x, acc[mf][j][1] + bv.y);
            *reinterpret_cast<float2*>(&g_gates[(size_t)(m + 8) * N4 + ncol]) =
                make_float2(acc[mf][j][2] + bv.x, acc[mf][j][3] + bv.y);
        }
    }
}

// ============================ RECURRENCE ====================================
// Grid (32 nb, 4 gm) = 128 CTAs, 256 threads, persistent.
// CTA tile: m = 32 gate-cols (m = g*8 + hl over 8 h-cols), n = 64 batches.
// Warp (wm = w>>2, nq = w&3): A = W slice m16 (wm: {g,i} or {f,o}) in REGISTERS
// (hi+lo, loaded once); B = h(t-1) fragments loaded DIRECTLY from global
// (k-interleaved layout -> one LDG.64 per fragment pair). No smem staging.
__global__ __launch_bounds__(256) void lstm_kernel(
    const float* __restrict__ Wg, const float* __restrict__ Wi,
    const float* __restrict__ Wf, const float* __restrict__ Wo)
{
    __shared__ float4 xbuf[8][32];

    const int tid = threadIdx.x;
    const int lane = tid & 31;
    const int w = tid >> 5;
    const int nq = w & 3;
    const int wm = w >> 2;
    const int nb = blockIdx.x;
    const int gm = blockIdx.y;
    const int r = lane >> 2;
    const int q = lane & 3;
    const int hcol = nb * 8 + r;

    // ---- W fragments in registers (once) ----
    uint32_t whi[16][4], wlo[16][4];
    {
        const float* WA = (wm == 0) ? Wg : Wf;   // rows +0  (gate 2*wm)
        const float* WB = (wm == 0) ? Wi : Wo;   // rows +8  (gate 2*wm+1)
        #pragma unroll
        for (int kk = 0; kk < 16; kk++) {
            #pragma unroll
            for (int j = 0; j < 4; j++) {
                const float* Wp = (j & 1) ? WB : WA;
                int col = q * 2 + ((j >> 1) & 1) * 8 + kk * 16;
                float w0 = __ldg(&Wp[col * H + hcol]);
                float w1 = __ldg(&Wp[(col + 1) * H + hcol]);
                __nv_bfloat16 h0 = __float2bfloat16(w0);
                __nv_bfloat16 h1 = __float2bfloat16(w1);
                whi[kk][j] = (uint32_t)reinterpret_cast<unsigned short&>(h0) |
                             ((uint32_t)reinterpret_cast<unsigned short&>(h1) << 16);
                wlo[kk][j] = pkbf(w0 - __bfloat162float(h0), w1 - __bfloat162float(h1));
            }
        }
    }

    // B-fragment n-rows (batches) and pointwise cells
    const int nB0 = gm * 64 + nq * 16 + r;            // block0 n-row
    const int bA = gm * 64 + nq * 16 + wm * 8 + q * 2; // pointwise cell A
    const int bB = bA + 1;

    // interleaved k position for this lane's h column
    const int kl = hcol & 15;
    const int kmem = (hcol & ~15) |
                     ((kl & 1) | (((kl >> 1) & 3) << 2) | (((kl >> 3) & 1) << 1));

    float cstA = 0.f, cstB = 0.f;

    for (int t = 0; t < T; t++) {
        // gate pre-activations (independent of h) — issue first
        float pA[4], pB[4];
        {
            size_t ga = ((size_t)bA * T + t) * N4 + hcol;
            size_t gb = ((size_t)bB * T + t) * N4 + hcol;
            #pragma unroll
            for (int g = 0; g < 4; g++) {
                pA[g] = __ldcg(&g_gates[ga + g * 256]);
                pB[g] = __ldcg(&g_gates[gb + g * 256]);
            }
        }

        float Gg[2] = {0.f, 0.f}, Gi[2] = {0.f, 0.f};
        float Gf[2] = {0.f, 0.f}, Go[2] = {0.f, 0.f};

        if (t > 0) {
            if (tid == 0) {
                unsigned need = 32u * (unsigned)t;
                unsigned v;
                do {
                    asm volatile("ld.acquire.gpu.global.u32 %0, [%1];"
                                 : "=r"(v) : "l"(&g_bar4[gm]) : "memory");
                } while (v < need);
            }
            __syncthreads();

            const char* phi = (const char*)g_hhi[(t + 1) & 1];
            const char* plo = (const char*)g_hlo[(t + 1) & 1];
            const size_t base0 = (size_t)nB0 * 512 + (size_t)q * 8;
            const size_t base1 = base0 + 8 * 512;

            float chh0[4] = {}, clh0[4] = {}, chl0[4] = {};
            float chh1[4] = {}, clh1[4] = {}, chl1[4] = {};

            #pragma unroll
            for (int kk = 0; kk < 16; kk++) {
                uint2 bh0 = __ldcg(reinterpret_cast<const uint2*>(phi + base0 + kk * 32));
                uint2 bl0 = __ldcg(reinterpret_cast<const uint2*>(plo + base0 + kk * 32));
                uint2 bh1 = __ldcg(reinterpret_cast<const uint2*>(phi + base1 + kk * 32));
                uint2 bl1 = __ldcg(reinterpret_cast<const uint2*>(plo + base1 + kk * 32));
                mma16816(chh0, whi[kk][0], whi[kk][1], whi[kk][2], whi[kk][3], bh0.x, bh0.y);
                mma16816(clh0, wlo[kk][0], wlo[kk][1], wlo[kk][2], wlo[kk][3], bh0.x, bh0.y);
                mma16816(chl0, whi[kk][0], whi[kk][1], whi[kk][2], whi[kk][3], bl0.x, bl0.y);
                mma16816(chh1, whi[kk][0], whi[kk][1], whi[kk][2], whi[kk][3], bh1.x, bh1.y);
                mma16816(clh1, wlo[kk][0], wlo[kk][1], wlo[kk][2], wlo[kk][3], bh1.x, bh1.y);
                mma16816(chl1, whi[kk][0], whi[kk][1], whi[kk][2], whi[kk][3], bl1.x, bl1.y);
            }

            float C0[4], C1[4];
            #pragma unroll
            for (int j = 0; j < 4; j++) {
                C0[j] = chh0[j] + clh0[j] + chl0[j];
                C1[j] = chh1[j] + clh1[j] + chl1[j];
            }

            // exchange the non-owned block with the partner warp (w ^ 4)
            const float* snd = (wm == 0) ? C1 : C0;
            xbuf[w][lane] = make_float4(snd[0], snd[1], snd[2], snd[3]);
            asm volatile("bar.sync %0, %1;" :: "r"(nq + 1), "r"(64) : "memory");
            float4 rcv = xbuf[w ^ 4][lane];
            const float* own = (wm == 0) ? C0 : C1;

            if (wm == 0) {
                Gg[0] = own[0]; Gg[1] = own[1];
                Gi[0] = own[2]; Gi[1] = own[3];
                Gf[0] = rcv.x;  Gf[1] = rcv.y;
                Go[0] = rcv.z;  Go[1] = rcv.w;
            } else {
                Gf[0] = own[0]; Gf[1] = own[1];
                Go[0] = own[2]; Go[1] = own[3];
                Gg[0] = rcv.x;  Gg[1] = rcv.y;
                Gi[0] = rcv.z;  Gi[1] = rcv.w;
            }
        }

        // pointwise (cells A, B); c in registers
        float gv = tanhf(pA[0] + Gg[0]);
        float iv = sigf (pA[1] + Gi[0]);
        float fv = sigf (pA[2] + Gf[0]);
        float ov = sigf (pA[3] + Go[0]);
        cstA = gv * iv + cstA * fv;
        float hA = tanhf(cstA) * ov;

        gv = tanhf(pB[0] + Gg[1]);
        iv = sigf (pB[1] + Gi[1]);
        fv = sigf (pB[2] + Gf[1]);
        ov = sigf (pB[3] + Go[1]);
        cstB = gv * iv + cstB * fv;
        float hB = tanhf(cstB) * ov;

        if (t < T - 1) {
            __nv_bfloat16 a0 = __float2bfloat16(hA);
            __nv_bfloat16 b0 = __float2bfloat16(hB);
            __nv_bfloat16 a1 = __float2bfloat16(hA - __bfloat162float(a0));
            __nv_bfloat16 b1 = __float2bfloat16(hB - __bfloat162float(b0));
            unsigned short* dhi = g_hhi[t & 1];
            unsigned short* dlo = g_hlo[t & 1];
            __stcg(&dhi[(size_t)bA * H + kmem], reinterpret_cast<unsigned short&>(a0));
            __stcg(&dhi[(size_t)bB * H + kmem], reinterpret_cast<unsigned short&>(b0));
            __stcg(&dlo[(size_t)bA * H + kmem], reinterpret_cast<unsigned short&>(a1));
            __stcg(&dlo[(size_t)bB * H + kmem], reinterpret_cast<unsigned short&>(b1));
            __syncthreads();
            if (tid == 0) {
                asm volatile("red.release.gpu.global.add.u32 [%0], %1;"
                             :: "l"(&g_bar4[gm]), "r"(1u) : "memory");
            }
        } else {
            g_hfin[(size_t)bA * H + hcol] = hA;
            g_hfin[(size_t)bB * H + hcol] = hB;
        }
    }
}

// ================================ HEAD ======================================
__global__ void final_kernel(const float* __restrict__ Wp,
                             const float* __restrict__ bp,
                             float* __restrict__ out)
{
    __shared__ float hsm[H];
    int b = blockIdx.x;
    hsm[threadIdx.x] = g_hfin[b * H + threadIdx.x];
    __syncthreads();
    if (threadIdx.x < C) {
        float acc = bp[threadIdx.x];
        #pragma unroll 8
        for (int k = 0; k < H; k++)
            acc += hsm[k] * Wp[k * C + threadIdx.x];
        out[b * C + threadIdx.x] = acc;
    }
}

// ---------------------------------------------------------------------------
extern "C" void kernel_launch(void* const* d_in, const int* in_sizes, int n_in,
                              void* d_out, int out_size)
{
    const float* x    = (const float*)d_in[0];
    const float* W_gx = (const float*)d_in[1];
    const float* W_ix = (const float*)d_in[2];
    const float* W_fx = (const float*)d_in[3];
    const float* W_ox = (const float*)d_in[4];
    const float* W_gh = (const float*)d_in[5];
    const float* W_ih = (const float*)d_in[6];
    const float* W_fh = (const float*)d_in[7];
    const float* W_oh = (const float*)d_in[8];
    const float* b_g  = (const float*)d_in[9];
    const float* b_i  = (const float*)d_in[10];
    const float* b_f  = (const float*)d_in[11];
    const float* b_o  = (const float*)d_in[12];
    const float* W_ph = (const float*)d_in[13];
    const float* b_p  = (const float*)d_in[14];
    float* out = (float*)d_out;

    static bool attr_set = false;
    if (!attr_set) {
        cudaFuncSetAttribute(projmma_kernel,
                             cudaFuncAttributeMaxDynamicSharedMemorySize, SMEM_PROJ);
        attr_set = true;
    }

    reset_kernel<<<1, 32>>>();

    projmma_kernel<<<dim3(N4 / 128, (B * T) / 128), 256, SMEM_PROJ>>>(
        x, W_gx, W_ix, W_fx, W_ox, b_g, b_i, b_f, b_o);

    lstm_kernel<<<dim3(32, 4), 256>>>(W_gh, W_ih, W_fh, W_oh);

    final_kernel<<<B, H>>>(W_ph, b_p, out);
}

// round 12
// speedup vs baseline: 2.3106x; 2.3106x over previous
#include <cuda_runtime.h>
#include <cuda_bf16.h>
#include <math.h>
#include <stdint.h>

#define B 256
#define D 128
#define T 512
#define H 256
#define C 10
#define N4 1024

// device scratch (no runtime allocation allowed)
__device__ float g_gates[(size_t)B * T * N4];        // [b][t][4H] fp32, 512 MB
__device__ unsigned short g_hhi[2][B * H];           // h bf16 hi, [b][k], dbl-buffered
__device__ unsigned short g_hlo[2][B * H];           // h bf16 lo
__device__ float g_hfin[B * H];                      // final h fp32
__device__ unsigned g_bar4[4];                       // per-m-group barriers

__device__ __forceinline__ float sigf(float x) { return 1.0f / (1.0f + expf(-x)); }

__global__ void reset_kernel() {
    if (threadIdx.x < 4) g_bar4[threadIdx.x] = 0u;
}

// no-op spacer: shifts lstm_kernel into the ncu capture slot
__global__ void dummy_kernel() {}

__device__ __forceinline__ uint32_t smem_u32(const void* p) {
    uint32_t a;
    asm("{ .reg .u64 t; cvta.to.shared.u64 t, %1; cvt.u32.u64 %0, t; }" : "=r"(a) : "l"(p));
    return a;
}
__device__ __forceinline__ void ldmx4(uint32_t& r0, uint32_t& r1, uint32_t& r2,
                                      uint32_t& r3, uint32_t addr) {
    asm volatile("ldmatrix.sync.aligned.m8n8.x4.shared.b16 {%0,%1,%2,%3}, [%4];"
                 : "=r"(r0), "=r"(r1), "=r"(r2), "=r"(r3) : "r"(addr));
}
__device__ __forceinline__ void ldmx4t(uint32_t* r, uint32_t addr) {
    asm volatile("ldmatrix.sync.aligned.m8n8.x4.trans.shared.b16 {%0,%1,%2,%3}, [%4];"
                 : "=r"(r[0]), "=r"(r[1]), "=r"(r[2]), "=r"(r[3]) : "r"(addr));
}
__device__ __forceinline__ void mma16816(float* c,
                                         uint32_t a0, uint32_t a1, uint32_t a2, uint32_t a3,
                                         uint32_t b0, uint32_t b1) {
    asm volatile(
        "mma.sync.aligned.m16n8k16.row.col.f32.bf16.bf16.f32 "
        "{%0,%1,%2,%3}, {%4,%5,%6,%7}, {%8,%9}, {%0,%1,%2,%3};"
        : "+f"(c[0]), "+f"(c[1]), "+f"(c[2]), "+f"(c[3])
        : "r"(a0), "r"(a1), "r"(a2), "r"(a3), "r"(b0), "r"(b1));
}
__device__ __forceinline__ uint32_t pkbf(float x, float y) {
    __nv_bfloat16 a = __float2bfloat16(x), b = __float2bfloat16(y);
    return (uint32_t)reinterpret_cast<unsigned short&>(a) |
           ((uint32_t)reinterpret_cast<unsigned short&>(b) << 16);
}

// ============================== PROJ (mma) ==================================
#define PPITCH 272
#define P_AHI 0
#define P_ALO (128 * PPITCH)
#define P_BHI (2 * 128 * PPITCH)
#define P_BLO (3 * 128 * PPITCH)
#define SMEM_PROJ (4 * 128 * PPITCH)

__global__ __launch_bounds__(256, 1) void projmma_kernel(
    const float* __restrict__ x,
    const float* __restrict__ Wg, const float* __restrict__ Wi,
    const float* __restrict__ Wf, const float* __restrict__ Wo,
    const float* __restrict__ bg, const float* __restrict__ bi,
    const float* __restrict__ bf, const float* __restrict__ bo)
{
    extern __shared__ char psm[];
    const uint32_t sb = smem_u32(psm);

    const int tid = threadIdx.x;
    const int lane = tid & 31;
    const int w = tid >> 5;
    const int wm2 = w & 3;
    const int nq2 = w >> 2;
    const int n0 = blockIdx.x * 128;
    const int m0 = blockIdx.y * 128;
    const int b  = m0 >> 9;
    const int t0 = m0 & 511;
    const int gate = n0 >> 8;
    const int hb = n0 & 255;

    const float* W    = (gate == 0) ? Wg : (gate == 1) ? Wi : (gate == 2) ? Wf : Wo;
    const float* bias = (gate == 0) ? bg : (gate == 1) ? bi : (gate == 2) ? bf : bo;

    #pragma unroll
    for (int i = 0; i < 16; i++) {
        int q = tid + i * 256;
        int k = q >> 5;
        int m4 = q & 31;
        float4 v = __ldcg(reinterpret_cast<const float4*>(
            &x[(size_t)b * (D * T) + k * T + t0 + m4 * 4]));
        float4 wv = __ldg(reinterpret_cast<const float4*>(&W[k * H + hb + m4 * 4]));
        uint32_t hiA0 = pkbf(v.x, v.y), hiA1 = pkbf(v.z, v.w);
        float rx = v.x - __bfloat162float(__float2bfloat16(v.x));
        float ry = v.y - __bfloat162float(__float2bfloat16(v.y));
        float rz = v.z - __bfloat162float(__float2bfloat16(v.z));
        float rw = v.w - __bfloat162float(__float2bfloat16(v.w));
        uint32_t loA0 = pkbf(rx, ry), loA1 = pkbf(rz, rw);
        uint32_t hiB0 = pkbf(wv.x, wv.y), hiB1 = pkbf(wv.z, wv.w);
        float sx = wv.x - __bfloat162float(__float2bfloat16(wv.x));
        float sy = wv.y - __bfloat162float(__float2bfloat16(wv.y));
        float sz = wv.z - __bfloat162float(__float2bfloat16(wv.z));
        float sw = wv.w - __bfloat162float(__float2bfloat16(wv.w));
        uint32_t loB0 = pkbf(sx, sy), loB1 = pkbf(sz, sw);
        uint32_t off = k * PPITCH + m4 * 8;
        *reinterpret_cast<uint2*>(psm + P_AHI + off) = make_uint2(hiA0, hiA1);
        *reinterpret_cast<uint2*>(psm + P_ALO + off) = make_uint2(loA0, loA1);
        *reinterpret_cast<uint2*>(psm + P_BHI + off) = make_uint2(hiB0, hiB1);
        *reinterpret_cast<uint2*>(psm + P_BLO + off) = make_uint2(loB0, loB1);
    }
    __syncthreads();

    const int sel = lane >> 3;
    const int lr  = lane & 7;
    const uint32_t aoff = (uint32_t)(((sel >> 1) * 8 + lr) * PPITCH + (sel & 1) * 16);
    const uint32_t boff = (uint32_t)(((sel & 1) * 8 + lr) * PPITCH + (sel >> 1) * 16);

    float acc[2][8][4] = {};

    #pragma unroll
    for (int kk = 0; kk < 8; kk++) {
        const uint32_t kb = kk * 16 * PPITCH;
        uint32_t ah[2][4], al[2][4], bh[4][4], bl[4][4];
        #pragma unroll
        for (int mf = 0; mf < 2; mf++) {
            uint32_t mcol = (wm2 * 32 + mf * 16) * 2;
            ldmx4t(ah[mf], sb + P_AHI + kb + aoff + mcol);
            ldmx4t(al[mf], sb + P_ALO + kb + aoff + mcol);
        }
        #pragma unroll
        for (int ng = 0; ng < 4; ng++) {
            uint32_t ncol = (nq2 * 64 + ng * 16) * 2;
            ldmx4t(bh[ng], sb + P_BHI + kb + boff + ncol);
            ldmx4t(bl[ng], sb + P_BLO + kb + boff + ncol);
        }
        #pragma unroll
        for (int mf = 0; mf < 2; mf++) {
            #pragma unroll
            for (int ng = 0; ng < 4; ng++) {
                float* c0 = acc[mf][ng * 2];
                float* c1 = acc[mf][ng * 2 + 1];
                mma16816(c0, ah[mf][0], ah[mf][1], ah[mf][2], ah[mf][3], bh[ng][0], bh[ng][1]);
                mma16816(c0, al[mf][0], al[mf][1], al[mf][2], al[mf][3], bh[ng][0], bh[ng][1]);
                mma16816(c0, ah[mf][0], ah[mf][1], ah[mf][2], ah[mf][3], bl[ng][0], bl[ng][1]);
                mma16816(c1, ah[mf][0], ah[mf][1], ah[mf][2], ah[mf][3], bh[ng][2], bh[ng][3]);
                mma16816(c1, al[mf][0], al[mf][1], al[mf][2], al[mf][3], bh[ng][2], bh[ng][3]);
                mma16816(c1, ah[mf][0], ah[mf][1], ah[mf][2], ah[mf][3], bl[ng][2], bl[ng][3]);
            }
        }
    }

    #pragma unroll
    for (int mf = 0; mf < 2; mf++) {
        int m = m0 + wm2 * 32 + mf * 16 + (lane >> 2);
        #pragma unroll
        for (int j = 0; j < 8; j++) {
            int hcol = hb + nq2 * 64 + j * 8 + (lane & 3) * 2;
            float2 bv = *reinterpret_cast<const float2*>(&bias[hcol]);
            int ncol = gate * 256 + hcol;
            *reinterpret_cast<float2*>(&g_gates[(size_t)m * N4 + ncol]) =
                make_float2(acc[mf][j][0] + bv.x, acc[mf][j][1] + bv.y);
            *reinterpret_cast<float2*>(&g_gates[(size_t)(m + 8) * N4 + ncol]) =
                make_float2(acc[mf][j][2] + bv.x, acc[mf][j][3] + bv.y);
        }
    }
}

// ============================ RECURRENCE ====================================
#define APITCHB 528
#define OFF_AHI 0
#define OFF_ALO (OFF_AHI + 64 * APITCHB)
#define OFF_BHI (OFF_ALO + 64 * APITCHB)
#define OFF_BLO (OFF_BHI + 32 * APITCHB)
#define OFF_CX  (OFF_BLO + 32 * APITCHB)
#define CXP 34
#define SMEM_LSTM (OFF_CX + 64 * CXP * 4)

__global__ __launch_bounds__(256, 1) void lstm_kernel(
    const float* __restrict__ Wg, const float* __restrict__ Wi,
    const float* __restrict__ Wf, const float* __restrict__ Wo)
{
    extern __shared__ char sm[];
    const uint32_t sb = smem_u32(sm);
    float* Cx = reinterpret_cast<float*>(sm + OFF_CX);

    const int tid = threadIdx.x;
    const int lane = tid & 31;
    const int w = tid >> 5;
    const int wm = w & 3;
    const int nq = w >> 2;
    const int nb = blockIdx.x;        // 0..31
    const int gm = blockIdx.y;        // 0..3
    const int hb8 = nb * 8;

    // Build W tile bf16 hi/lo in smem once: B[n][k], n = g*8+hl
    for (int idx = tid; idx < 32 * 256; idx += 256) {
        int k = idx >> 5;
        int n = idx & 31;
        int g = n >> 3, hl = n & 7;
        const float* W = (g == 0) ? Wg : (g == 1) ? Wi : (g == 2) ? Wf : Wo;
        float wv = W[k * H + hb8 + hl];
        __nv_bfloat16 bh = __float2bfloat16(wv);
        __nv_bfloat16 bl = __float2bfloat16(wv - __bfloat162float(bh));
        *reinterpret_cast<unsigned short*>(sm + OFF_BHI + n * APITCHB + k * 2) =
            reinterpret_cast<unsigned short&>(bh);
        *reinterpret_cast<unsigned short*>(sm + OFF_BLO + n * APITCHB + k * 2) =
            reinterpret_cast<unsigned short&>(bl);
    }
    __syncthreads();

    const uint32_t a_row = wm * 16 + (lane & 7) + ((lane >> 3) & 1) * 8;
    const uint32_t a_base = a_row * APITCHB + (lane >> 4) * 16;
    const uint32_t b_row = nq * 16 + (lane >> 4) * 8 + (lane & 7);
    const uint32_t b_base = b_row * APITCHB + ((lane >> 3) & 1) * 16;

    const int bl_ = tid >> 2;
    const int hl2 = (tid & 3) * 2;
    const int bglob = gm * 64 + bl_;

    float2 cstate = make_float2(0.f, 0.f);

    for (int t = 0; t < T; t++) {
        float2 pg, pi_, pf_, po;
        {
            const size_t rb = ((size_t)bglob * T + t) * N4 + hb8 + hl2;
            pg  = __ldcg(reinterpret_cast<const float2*>(&g_gates[rb]));
            pi_ = __ldcg(reinterpret_cast<const float2*>(&g_gates[rb + 256]));
            pf_ = __ldcg(reinterpret_cast<const float2*>(&g_gates[rb + 512]));
            po  = __ldcg(reinterpret_cast<const float2*>(&g_gates[rb + 768]));
        }

        float2 ag = make_float2(0.f, 0.f), ai = ag, af = ag, ao = ag;

        if (t > 0) {
            __syncthreads();
            if (tid == 0) {
                unsigned need = (unsigned)(32 * t);
                unsigned v;
                do {
                    asm volatile("ld.acquire.gpu.global.u32 %0, [%1];"
                                 : "=r"(v) : "l"(&g_bar4[gm]) : "memory");
                } while (v < need);
            }
            __syncthreads();

            const unsigned short* src_hi = g_hhi[(t + 1) & 1];
            const unsigned short* src_lo = g_hlo[(t + 1) & 1];
            #pragma unroll
            for (int i = 0; i < 8; i++) {
                int idx = tid + i * 256;
                int m = idx >> 5;
                int ch = idx & 31;
                size_t gidx = (size_t)(gm * 64 + m) * H + ch * 8;
                uint4 vh = __ldcg(reinterpret_cast<const uint4*>(&src_hi[gidx]));
                uint4 vl = __ldcg(reinterpret_cast<const uint4*>(&src_lo[gidx]));
                *reinterpret_cast<uint4*>(sm + OFF_AHI + m * APITCHB + ch * 16) = vh;
                *reinterpret_cast<uint4*>(sm + OFF_ALO + m * APITCHB + ch * 16) = vl;
            }
            __syncthreads();

            float c0[4] = {0.f, 0.f, 0.f, 0.f};
            float c1[4] = {0.f, 0.f, 0.f, 0.f};
            #pragma unroll
            for (int kk = 0; kk < 16; kk++) {
                uint32_t ah[4], al[4], bh[4], blx[4];
                ldmx4(ah[0], ah[1], ah[2], ah[3], sb + OFF_AHI + a_base + kk * 32);
                ldmx4(al[0], al[1], al[2], al[3], sb + OFF_ALO + a_base + kk * 32);
                ldmx4(bh[0], bh[1], bh[2], bh[3], sb + OFF_BHI + b_base + kk * 32);
                ldmx4(blx[0], blx[1], blx[2], blx[3], sb + OFF_BLO + b_base + kk * 32);
                mma16816(c0, ah[0], ah[1], ah[2], ah[3], bh[0], bh[1]);
                mma16816(c0, al[0], al[1], al[2], al[3], bh[0], bh[1]);
                mma16816(c0, ah[0], ah[1], ah[2], ah[3], blx[0], blx[1]);
                mma16816(c1, ah[0], ah[1], ah[2], ah[3], bh[2], bh[3]);
                mma16816(c1, al[0], al[1], al[2], al[3], bh[2], bh[3]);
                mma16816(c1, ah[0], ah[1], ah[2], ah[3], blx[2], blx[3]);
            }

            {
                int crow = wm * 16 + (lane >> 2);
                int ccol = nq * 16 + (lane & 3) * 2;
                *reinterpret_cast<float2*>(&Cx[crow * CXP + ccol]) = make_float2(c0[0], c0[1]);
                *reinterpret_cast<float2*>(&Cx[(crow + 8) * CXP + ccol]) = make_float2(c0[2], c0[3]);
                *reinterpret_cast<float2*>(&Cx[crow * CXP + ccol + 8]) = make_float2(c1[0], c1[1]);
                *reinterpret_cast<float2*>(&Cx[(crow + 8) * CXP + ccol + 8]) = make_float2(c1[2], c1[3]);
            }
            __syncthreads();

            ag = *reinterpret_cast<float2*>(&Cx[bl_ * CXP + 0 * 8 + hl2]);
            ai = *reinterpret_cast<float2*>(&Cx[bl_ * CXP + 1 * 8 + hl2]);
            af = *reinterpret_cast<float2*>(&Cx[bl_ * CXP + 2 * 8 + hl2]);
            ao = *reinterpret_cast<float2*>(&Cx[bl_ * CXP + 3 * 8 + hl2]);
        }

        float hx = tanhf(pg.x + ag.x);
        float hy = tanhf(pg.y + ag.y);
        float ix = sigf(pi_.x + ai.x);
        float iy = sigf(pi_.y + ai.y);
        float fx = sigf(pf_.x + af.x);
        float fy = sigf(pf_.y + af.y);
        float ox = sigf(po.x + ao.x);
        float oy = sigf(po.y + ao.y);
        cstate.x = hx * ix + cstate.x * fx;
        cstate.y = hy * iy + cstate.y * fy;
        float h0 = tanhf(cstate.x) * ox;
        float h1 = tanhf(cstate.y) * oy;

        if (t < T - 1) {
            unsigned uhi = pkbf(h0, h1);
            __nv_bfloat16 q0 = __float2bfloat16(h0);
            __nv_bfloat16 q1 = __float2bfloat16(h1);
            unsigned ulo = pkbf(h0 - __bfloat162float(q0), h1 - __bfloat162float(q1));
            size_t hidx = (size_t)bglob * H + hb8 + hl2;
            __stcg(reinterpret_cast<unsigned*>(&g_hhi[t & 1][hidx]), uhi);
            __stcg(reinterpret_cast<unsigned*>(&g_hlo[t & 1][hidx]), ulo);
            __syncthreads();
            if (tid == 0) {
                asm volatile("red.release.gpu.global.add.u32 [%0], %1;"
                             :: "l"(&g_bar4[gm]), "r"(1u) : "memory");
            }
        } else {
            *reinterpret_cast<float2*>(&g_hfin[(size_t)bglob * H + hb8 + hl2]) =
                make_float2(h0, h1);
        }
    }
}

// ================================ HEAD ======================================
__global__ void final_kernel(const float* __restrict__ Wp,
                             const float* __restrict__ bp,
                             float* __restrict__ out)
{
    __shared__ float hsm[H];
    int b = blockIdx.x;
    hsm[threadIdx.x] = g_hfin[b * H + threadIdx.x];
    __syncthreads();
    if (threadIdx.x < C) {
        float acc = bp[threadIdx.x];
        #pragma unroll 8
        for (int k = 0; k < H; k++)
            acc += hsm[k] * Wp[k * C + threadIdx.x];
        out[b * C + threadIdx.x] = acc;
    }
}

// ---------------------------------------------------------------------------
extern "C" void kernel_launch(void* const* d_in, const int* in_sizes, int n_in,
                              void* d_out, int out_size)
{
    const float* x    = (const float*)d_in[0];
    const float* W_gx = (const float*)d_in[1];
    const float* W_ix = (const float*)d_in[2];
    const float* W_fx = (const float*)d_in[3];
    const float* W_ox = (const float*)d_in[4];
    const float* W_gh = (const float*)d_in[5];
    const float* W_ih = (const float*)d_in[6];
    const float* W_fh = (const float*)d_in[7];
    const float* W_oh = (const float*)d_in[8];
    const float* b_g  = (const float*)d_in[9];
    const float* b_i  = (const float*)d_in[10];
    const float* b_f  = (const float*)d_in[11];
    const float* b_o  = (const float*)d_in[12];
    const float* W_ph = (const float*)d_in[13];
    const float* b_p  = (const float*)d_in[14];
    float* out = (float*)d_out;

    static bool attr_set = false;
    if (!attr_set) {
        cudaFuncSetAttribute(lstm_kernel,
                             cudaFuncAttributeMaxDynamicSharedMemorySize, SMEM_LSTM);
        cudaFuncSetAttribute(projmma_kernel,
                             cudaFuncAttributeMaxDynamicSharedMemorySize, SMEM_PROJ);
        attr_set = true;
    }

    reset_kernel<<<1, 32>>>();

    projmma_kernel<<<dim3(N4 / 128, (B * T) / 128), 256, SMEM_PROJ>>>(
        x, W_gx, W_ix, W_fx, W_ox, b_g, b_i, b_f, b_o);

    // spacer so lstm_kernel lands in the ncu capture slot (user launch #4)
    dummy_kernel<<<1, 32>>>();

    lstm_kernel<<<dim3(32, 4), 256, SMEM_LSTM>>>(W_gh, W_ih, W_fh, W_oh);

    final_kernel<<<B, H>>>(W_ph, b_p, out);
}